// round 12
// baseline (speedup 1.0000x reference)
#include <cuda_runtime.h>
#include <cuda_fp16.h>
#include <math_constants.h>
#include <cstdint>

#define NMAX 16384
#define DMAX 512
#define MARGIN 0.3f
#define EPS 1e-12f

#define TM 128
#define TN 256
#define COLSPLIT 2

__device__ float  g_sq[NMAX];
__device__ int    g_lab[NMAX];
__device__ int    g_ap_bits[NMAX];
__device__ int    g_an_bits[NMAX];
__device__ __half g_xh[(size_t)NMAX * DMAX];

// ---------------- PTX helpers ----------------
__device__ __forceinline__ uint32_t smem_u32(const void* p) {
    uint32_t a;
    asm("{ .reg .u64 t; cvta.to.shared.u64 t, %1; cvt.u32.u64 %0, t; }"
        : "=r"(a) : "l"(p));
    return a;
}
#define CP_ASYNC16(dst, src) \
    asm volatile("cp.async.cg.shared.global [%0], [%1], 16;" \
                 :: "r"(dst), "l"(src) : "memory")
#define CP_COMMIT() asm volatile("cp.async.commit_group;" ::: "memory")
#define CP_WAIT1()  asm volatile("cp.async.wait_group 1;" ::: "memory")

__device__ __forceinline__ void ldsm_x4(uint32_t* r, uint32_t addr) {
    asm volatile("ldmatrix.sync.aligned.m8n8.x4.shared.b16 {%0,%1,%2,%3}, [%4];"
                 : "=r"(r[0]), "=r"(r[1]), "=r"(r[2]), "=r"(r[3]) : "r"(addr));
}
__device__ __forceinline__ void mma_f16(float* c, uint32_t a0, uint32_t a1,
                                        uint32_t a2, uint32_t a3,
                                        uint32_t b0, uint32_t b1) {
    asm volatile(
        "mma.sync.aligned.m16n8k16.row.col.f32.f16.f16.f32 "
        "{%0,%1,%2,%3}, {%4,%5,%6,%7}, {%8,%9}, {%0,%1,%2,%3};"
        : "+f"(c[0]), "+f"(c[1]), "+f"(c[2]), "+f"(c[3])
        : "r"(a0), "r"(a1), "r"(a2), "r"(a3), "r"(b0), "r"(b1));
}

// ---- labels (int32 or int64 on disk) -> g_lab int32; also init ap/an ----
__global__ void label_kernel(const int* __restrict__ traw, int n) {
    __shared__ int odd_nonzero;
    if (threadIdx.x == 0) odd_nonzero = 0;
    __syncthreads();
    int m = (n < 128) ? n : 128;
    for (int i = threadIdx.x; i < m; i += blockDim.x)
        if (traw[2 * i + 1] != 0) atomicOr(&odd_nonzero, 1);
    __syncthreads();
    bool is64 = (odd_nonzero == 0);
    for (int i = threadIdx.x; i < n; i += blockDim.x) {
        g_lab[i] = is64 ? traw[2 * i] : traw[i];
        g_ap_bits[i] = 0;
        g_an_bits[i] = 0x7f800000;
    }
}

// ---- fused fp32->fp16 convert + exact fp32 sq-norm: one warp per row ----
__global__ void prep_kernel(const float* __restrict__ X, int n, int d) {
    int warp = (blockIdx.x * blockDim.x + threadIdx.x) >> 5;
    int lane = threadIdx.x & 31;
    if (warp >= n) return;
    const float4* row = (const float4*)(X + (size_t)warp * d);
    __half2* orow = (__half2*)(g_xh + (size_t)warp * d);
    float s = 0.f;
    for (int k = lane; k < d / 4; k += 32) {
        float4 v = row[k];
        s = fmaf(v.x, v.x, s); s = fmaf(v.y, v.y, s);
        s = fmaf(v.z, v.z, s); s = fmaf(v.w, v.w, s);
        orow[2 * k]     = __floats2half2_rn(v.x, v.y);
        orow[2 * k + 1] = __floats2half2_rn(v.z, v.w);
    }
    #pragma unroll
    for (int off = 16; off; off >>= 1)
        s += __shfl_xor_sync(0xffffffffu, s, off);
    if (lane == 0) g_sq[warp] = s;
}

// --------- fused fp16 mma gram + d^2 + hardest pos/neg ----------
// 512 threads, 16 warps (4 M x 4 N), warp tile 32x64.
// A persistent (TM x d fp16), B double-buffered via cp.async, ldmatrix frags.
__global__ __launch_bounds__(512, 1)
void dist_mma_kernel(int n, int d) {
    extern __shared__ char dyn[];
    __shared__ int   tCs[TN];
    __shared__ float sCs[TN];
    __shared__ int   tRs[TM];
    __shared__ float sRs[TM];

    const int tid  = threadIdx.x;          // 512 threads = 16 warps
    const int wid  = tid >> 5;
    const int lane = tid & 31;
    const int wm   = wid & 3;              // 4 warps along M (32 rows each)
    const int wn   = wid >> 2;             // 4 warps along N (64 cols each)
    const int gID  = lane >> 2;
    const int tig  = lane & 3;

    const int rowBase = blockIdx.x * TM;
    const int colBase = blockIdx.y * (n / COLSPLIT);
    const int nJt  = (n / COLSPLIT) / TN;
    const int nStA = d / 64;               // 64-half K stages (8 for d=512)
    const int total = nJt * nStA;

    const uint32_t dynA = smem_u32(dyn);
    const uint32_t dynB = dynA + nStA * 16384;
    const __half* Xh = g_xh;

    // ---------------- prologue fills ----------------
    // A: all stages (persistent). 1024 16B units per stage / 512 threads = 2
    for (int st = 0; st < nStA; st++) {
        #pragma unroll
        for (int u = 0; u < 2; u++) {
            int idx = u * 512 + tid;
            int r = idx >> 3, q = idx & 7;
            uint32_t dst = dynA + st * 16384 + r * 128 + ((q * 16) ^ ((r & 7) << 4));
            const __half* src = Xh + (size_t)(rowBase + r) * d + st * 64 + q * 8;
            CP_ASYNC16(dst, src);
        }
    }
    // B stage 0 (buf 0): 2048 units / 512 = 4
    {
        #pragma unroll
        for (int u = 0; u < 4; u++) {
            int idx = u * 512 + tid;
            int r = idx >> 3, q = idx & 7;
            uint32_t dst = dynB + r * 128 + ((q * 16) ^ ((r & 7) << 4));
            const __half* src = Xh + (size_t)(colBase + r) * d + q * 8;
            CP_ASYNC16(dst, src);
        }
    }
    CP_COMMIT();           // group: A + B0
    // B stage 1 (buf 1)
    if (total > 1) {
        int jt2 = 1 / nStA, kc2 = 1 % nStA;
        int cT2 = colBase + jt2 * TN;
        #pragma unroll
        for (int u = 0; u < 4; u++) {
            int idx = u * 512 + tid;
            int r = idx >> 3, q = idx & 7;
            uint32_t dst = dynB + 32768 + r * 128 + ((q * 16) ^ ((r & 7) << 4));
            const __half* src = Xh + (size_t)(cT2 + r) * d + kc2 * 64 + q * 8;
            CP_ASYNC16(dst, src);
        }
    }
    CP_COMMIT();

    // row metadata into shared
    if (tid < TM) {
        tRs[tid] = g_lab[rowBase + tid];
        sRs[tid] = g_sq[rowBase + tid];
    }

    // frag address precompute
    const int xorv = (lane & 7) << 4;
    const uint32_t aRowOff = (uint32_t)(wm * 32 + (lane & 15)) * 128;
    const uint32_t bRowOff = (uint32_t)(wn * 64 + ((lane >> 4) & 1) * 8 + (lane & 7)) * 128;
    int kA[4], kB[4];
    #pragma unroll
    for (int blk = 0; blk < 4; blk++) {
        kA[blk] = (blk * 32 + (lane >> 4) * 16) ^ xorv;
        kB[blk] = (blk * 32 + ((lane >> 3) & 1) * 16) ^ xorv;
    }

    float acc[2][8][4];
    #pragma unroll
    for (int ma = 0; ma < 2; ma++)
        #pragma unroll
        for (int na = 0; na < 8; na++)
            #pragma unroll
            for (int f = 0; f < 4; f++) acc[ma][na][f] = 0.f;

    float apd2[4], and2[4];
    #pragma unroll
    for (int i = 0; i < 4; i++) { apd2[i] = 0.f; and2[i] = CUDART_INF_F; }

    int kcIdx = 0, jt = 0;
    for (int s = 0; s < total; s++) {
        const int cTile = colBase + jt * TN;
        CP_WAIT1();
        __syncthreads();                    // fill(s) visible to all warps

        if (kcIdx == 0 && tid < TN) {
            tCs[tid] = g_lab[cTile + tid];
            sCs[tid] = g_sq[cTile + tid];
        }

        // ---- MMA over 4 k16 blocks of this stage ----
        const uint32_t Ast = dynA + kcIdx * 16384 + aRowOff;
        const uint32_t Bst = dynB + (s & 1) * 32768 + bRowOff;
        #pragma unroll
        for (int blk = 0; blk < 4; blk++) {
            uint32_t a[2][4], b[4][4];
            #pragma unroll
            for (int ma = 0; ma < 2; ma++)
                ldsm_x4(a[ma], Ast + ma * 2048 + kA[blk]);
            #pragma unroll
            for (int p = 0; p < 4; p++)
                ldsm_x4(b[p], Bst + p * 2048 + kB[blk]);
            #pragma unroll
            for (int ma = 0; ma < 2; ma++)
                #pragma unroll
                for (int p = 0; p < 4; p++) {
                    mma_f16(acc[ma][2 * p],     a[ma][0], a[ma][1], a[ma][2], a[ma][3],
                            b[p][0], b[p][1]);
                    mma_f16(acc[ma][2 * p + 1], a[ma][0], a[ma][1], a[ma][2], a[ma][3],
                            b[p][2], b[p][3]);
                }
        }

        // ---- epilogue at last k-stage of this jt ----
        if (kcIdx == nStA - 1) {
            #pragma unroll
            for (int ma = 0; ma < 2; ma++) {
                #pragma unroll
                for (int h = 0; h < 2; h++) {
                    int rloc = wm * 32 + ma * 16 + gID + 8 * h;
                    int rg   = rowBase + rloc;
                    int rT   = tRs[rloc];
                    float rS = sRs[rloc];
                    int ridx = ma * 2 + h;
                    #pragma unroll
                    for (int na = 0; na < 8; na++)
                        #pragma unroll
                        for (int j = 0; j < 2; j++) {
                            int col = wn * 64 + na * 8 + tig * 2 + j;
                            int cg  = cTile + col;
                            float d2 = rS + sCs[col] - 2.f * acc[ma][na][2 * h + j];
                            if (cg == rg) d2 = EPS;
                            d2 = fmaxf(d2, EPS);
                            if (rT == tCs[col]) apd2[ridx] = fmaxf(apd2[ridx], d2);
                            else                and2[ridx] = fminf(and2[ridx], d2);
                            acc[ma][na][2 * h + j] = 0.f;
                        }
                }
            }
        }

        __syncthreads();                    // all warps done with buf (s&1)
        // ---- issue fill for stage s+2 into buf (s&1) ----
        int s2 = s + 2;
        if (s2 < total) {
            int jt2 = s2 / nStA, kc2 = s2 % nStA;
            int cT2 = colBase + jt2 * TN;
            #pragma unroll
            for (int u = 0; u < 4; u++) {
                int idx = u * 512 + tid;
                int r = idx >> 3, q = idx & 7;
                uint32_t dst = dynB + (s2 & 1) * 32768 + r * 128 +
                               ((q * 16) ^ ((r & 7) << 4));
                const __half* src = Xh + (size_t)(cT2 + r) * d + kc2 * 64 + q * 8;
                CP_ASYNC16(dst, src);
            }
        }
        CP_COMMIT();

        if (++kcIdx == nStA) { kcIdx = 0; jt++; }
    }

    // reduce across the quad (same rows, different cols per tig)
    #pragma unroll
    for (int off = 1; off <= 2; off <<= 1)
        #pragma unroll
        for (int i = 0; i < 4; i++) {
            apd2[i] = fmaxf(apd2[i], __shfl_xor_sync(0xffffffffu, apd2[i], off));
            and2[i] = fminf(and2[i], __shfl_xor_sync(0xffffffffu, and2[i], off));
        }
    if (tig == 0) {
        #pragma unroll
        for (int ma = 0; ma < 2; ma++)
            #pragma unroll
            for (int h = 0; h < 2; h++) {
                int rg = rowBase + wm * 32 + ma * 16 + gID + 8 * h;
                atomicMax(&g_ap_bits[rg], __float_as_int(apd2[ma * 2 + h]));
                atomicMin(&g_an_bits[rg], __float_as_int(and2[ma * 2 + h]));
            }
    }
}

// ---------------- final mean(relu(sqrt(ap2) - sqrt(an2) + margin)) --------
__global__ void loss_kernel(int n, float* __restrict__ out) {
    __shared__ float red[1024];
    int tid = threadIdx.x;
    float s = 0.f;
    for (int i = tid; i < n; i += blockDim.x) {
        float ap = sqrtf(fmaxf(__int_as_float(g_ap_bits[i]), EPS));
        float an = sqrtf(fmaxf(__int_as_float(g_an_bits[i]), EPS));
        s += fmaxf(ap - an + MARGIN, 0.f);
    }
    red[tid] = s;
    __syncthreads();
    for (int off = blockDim.x >> 1; off; off >>= 1) {
        if (tid < off) red[tid] += red[tid + off];
        __syncthreads();
    }
    if (tid == 0) out[0] = red[0] / (float)n;
}

extern "C" void kernel_launch(void* const* d_in, const int* in_sizes, int n_in,
                              void* d_out, int out_size) {
    const float* X    = (const float*)d_in[0];
    const int*   traw = (const int*)d_in[1];
    float* out = (float*)d_out;
    int n = in_sizes[1];
    int d = in_sizes[0] / n;

    int nStA = d / 64;
    int dynBytes = nStA * 16384 + 2 * 32768;   // A persistent + B double buffer
    cudaFuncSetAttribute(dist_mma_kernel,
                         cudaFuncAttributeMaxDynamicSharedMemorySize, dynBytes);

    label_kernel<<<1, 256>>>(traw, n);

    int warpsPerBlock = 8;
    int nb = (n + warpsPerBlock - 1) / warpsPerBlock;
    prep_kernel<<<nb, warpsPerBlock * 32>>>(X, n, d);

    dim3 grid(n / TM, COLSPLIT);
    dist_mma_kernel<<<grid, 512, dynBytes>>>(n, d);

    loss_kernel<<<1, 1024>>>(n, out);
}

// round 13
// speedup vs baseline: 2.0002x; 2.0002x over previous
#include <cuda_runtime.h>
#include <cuda_fp16.h>
#include <math_constants.h>
#include <cstdint>

#define NMAX 16384
#define DMAX 512
#define MARGIN 0.3f
#define EPS 1e-12f

__device__ float  g_sq[NMAX];
__device__ int    g_lab[NMAX];
__device__ int    g_ap_bits[NMAX];
__device__ int    g_an_bits[NMAX];
__device__ __half g_xh[(size_t)NMAX * DMAX];

// ---------------- PTX helpers ----------------
__device__ __forceinline__ uint32_t smem_u32(const void* p) {
    uint32_t a;
    asm("{ .reg .u64 t; cvta.to.shared.u64 t, %1; cvt.u32.u64 %0, t; }"
        : "=r"(a) : "l"(p));
    return a;
}
#define CP_ASYNC16(dst, src) \
    asm volatile("cp.async.cg.shared.global [%0], [%1], 16;" \
                 :: "r"(dst), "l"(src) : "memory")
#define CP_COMMIT() asm volatile("cp.async.commit_group;" ::: "memory")
#define CP_WAIT1()  asm volatile("cp.async.wait_group 1;" ::: "memory")

__device__ __forceinline__ void ldsm_x4(uint32_t* r, uint32_t addr) {
    asm volatile("ldmatrix.sync.aligned.m8n8.x4.shared.b16 {%0,%1,%2,%3}, [%4];"
                 : "=r"(r[0]), "=r"(r[1]), "=r"(r[2]), "=r"(r[3]) : "r"(addr));
}
__device__ __forceinline__ void mma_f16(float* c, uint32_t a0, uint32_t a1,
                                        uint32_t a2, uint32_t a3,
                                        uint32_t b0, uint32_t b1) {
    asm volatile(
        "mma.sync.aligned.m16n8k16.row.col.f32.f16.f16.f32 "
        "{%0,%1,%2,%3}, {%4,%5,%6,%7}, {%8,%9}, {%0,%1,%2,%3};"
        : "+f"(c[0]), "+f"(c[1]), "+f"(c[2]), "+f"(c[3])
        : "r"(a0), "r"(a1), "r"(a2), "r"(a3), "r"(b0), "r"(b1));
}

// ---- labels (int32 or int64 on disk) -> g_lab int32; also init ap/an ----
__global__ void label_kernel(const int* __restrict__ traw, int n) {
    __shared__ int odd_nonzero;
    if (threadIdx.x == 0) odd_nonzero = 0;
    __syncthreads();
    int m = (n < 128) ? n : 128;
    for (int i = threadIdx.x; i < m; i += blockDim.x)
        if (traw[2 * i + 1] != 0) atomicOr(&odd_nonzero, 1);
    __syncthreads();
    bool is64 = (odd_nonzero == 0);
    for (int i = threadIdx.x; i < n; i += blockDim.x) {
        g_lab[i] = is64 ? traw[2 * i] : traw[i];
        g_ap_bits[i] = 0;
        g_an_bits[i] = 0x7f800000;
    }
}

// ---- fused fp32->fp16 convert + exact fp32 sq-norm: one warp per row ----
__global__ void prep_kernel(const float* __restrict__ X, int n, int d) {
    int warp = (blockIdx.x * blockDim.x + threadIdx.x) >> 5;
    int lane = threadIdx.x & 31;
    if (warp >= n) return;
    const float4* row = (const float4*)(X + (size_t)warp * d);
    __half2* orow = (__half2*)(g_xh + (size_t)warp * d);
    float s = 0.f;
    for (int k = lane; k < d / 4; k += 32) {
        float4 v = row[k];
        s = fmaf(v.x, v.x, s); s = fmaf(v.y, v.y, s);
        s = fmaf(v.z, v.z, s); s = fmaf(v.w, v.w, s);
        orow[2 * k]     = __floats2half2_rn(v.x, v.y);
        orow[2 * k + 1] = __floats2half2_rn(v.z, v.w);
    }
    #pragma unroll
    for (int off = 16; off; off >>= 1)
        s += __shfl_xor_sync(0xffffffffu, s, off);
    if (lane == 0) g_sq[warp] = s;
}

// --------- symmetric fp16 mma gram + d^2 + hardest pos/neg ----------
// One CTA per block-pair (I <= J) of 128x128. Off-diagonal CTAs update both
// row-side (rows of I) and col-side (rows of J) reductions from one GEMM.
// 8 warps (2 M x 4 N), warp tile 64x32, 3-stage cp.async pipeline.
__global__ __launch_bounds__(256, 2)
void dist_mma_kernel(int n, int d) {
    extern __shared__ char dyn[];
    __shared__ int   tRs[128];
    __shared__ float sRs[128];
    __shared__ int   tCs[128];
    __shared__ float sCs[128];

    const int tid  = threadIdx.x;          // 256 threads = 8 warps
    const int wid  = tid >> 5;
    const int lane = tid & 31;
    const int wm   = wid & 1;              // 2 warps along M (64 rows each)
    const int wn   = wid >> 1;             // 4 warps along N (32 cols each)
    const int gID  = lane >> 2;
    const int tig  = lane & 3;

    // ---- triangle mapping: blockIdx.x -> (I, J), I <= J ----
    const int nB = n >> 7;
    const int idx = blockIdx.x;
    // f(i) = pairs before row i = i*nB - i*(i-1)/2
    int I = (int)((2.f * nB + 1.f -
                   sqrtf((2.f * nB + 1.f) * (2.f * nB + 1.f) - 8.f * (float)idx)) * 0.5f);
    if (I < 0) I = 0;
    if (I > nB - 1) I = nB - 1;
    while (I > 0 && (I * nB - (I * (I - 1)) / 2) > idx) I--;
    while (((I + 1) * nB - ((I + 1) * I) / 2) <= idx) I++;
    const int J = I + (idx - (I * nB - (I * (I - 1)) / 2));
    const bool diag = (I == J);

    const int rowBase = I << 7;
    const int colBase = J << 7;
    const int nSt = d >> 6;                // 64-half K stages (8 for d=512)

    const uint32_t dynbase = smem_u32(dyn);
    const __half* Xh = g_xh;

    // metadata
    if (tid < 128)       { tRs[tid] = g_lab[rowBase + tid];
                           sRs[tid] = g_sq[rowBase + tid]; }
    else                 { tCs[tid - 128] = g_lab[colBase + tid - 128];
                           sCs[tid - 128] = g_sq[colBase + tid - 128]; }

    // ---- pipeline prologue: stages 0, 1 ----
    #pragma unroll
    for (int st = 0; st < 2; st++) {
        uint32_t bufA = dynbase + st * 32768;
        uint32_t bufB = bufA + 16384;
        #pragma unroll
        for (int u = 0; u < 4; u++) {
            int t2 = u * 256 + tid;
            int r = t2 >> 3, q = t2 & 7;
            uint32_t off = r * 128 + ((q * 16) ^ ((r & 7) << 4));
            CP_ASYNC16(bufA + off, Xh + (size_t)(rowBase + r) * d + st * 64 + q * 8);
            CP_ASYNC16(bufB + off, Xh + (size_t)(colBase + r) * d + st * 64 + q * 8);
        }
        CP_COMMIT();
    }

    // frag address precompute (verified mapping from R11)
    const int xorv = (lane & 7) << 4;
    const uint32_t aRowOff = (uint32_t)(wm * 64 + (lane & 15)) * 128;
    const uint32_t bRowOff = (uint32_t)(wn * 32 + ((lane >> 4) & 1) * 8 + (lane & 7)) * 128;
    int kA[4], kB[4];
    #pragma unroll
    for (int blk = 0; blk < 4; blk++) {
        kA[blk] = (blk * 32 + (lane >> 4) * 16) ^ xorv;
        kB[blk] = (blk * 32 + ((lane >> 3) & 1) * 16) ^ xorv;
    }

    float acc[4][4][4];
    #pragma unroll
    for (int ma = 0; ma < 4; ma++)
        #pragma unroll
        for (int na = 0; na < 4; na++)
            #pragma unroll
            for (int f = 0; f < 4; f++) acc[ma][na][f] = 0.f;

    // ---- main K loop (pure GEMM) ----
    for (int k = 0; k < nSt; k++) {
        CP_WAIT1();
        __syncthreads();                   // stage k visible to all warps

        // prefetch stage k+2 into buffer (k+2)%3 (free: consumed at k-1)
        int k2 = k + 2;
        if (k2 < nSt) {
            uint32_t bufA = dynbase + (k2 % 3) * 32768;
            uint32_t bufB = bufA + 16384;
            #pragma unroll
            for (int u = 0; u < 4; u++) {
                int t2 = u * 256 + tid;
                int r = t2 >> 3, q = t2 & 7;
                uint32_t off = r * 128 + ((q * 16) ^ ((r & 7) << 4));
                CP_ASYNC16(bufA + off, Xh + (size_t)(rowBase + r) * d + k2 * 64 + q * 8);
                CP_ASYNC16(bufB + off, Xh + (size_t)(colBase + r) * d + k2 * 64 + q * 8);
            }
        }
        CP_COMMIT();

        const uint32_t Ast = dynbase + (k % 3) * 32768 + aRowOff;
        const uint32_t Bst = dynbase + (k % 3) * 32768 + 16384 + bRowOff;
        #pragma unroll
        for (int blk = 0; blk < 4; blk++) {
            uint32_t a[4][4], b[2][4];
            #pragma unroll
            for (int ma = 0; ma < 4; ma++)
                ldsm_x4(a[ma], Ast + ma * 2048 + kA[blk]);
            #pragma unroll
            for (int p = 0; p < 2; p++)
                ldsm_x4(b[p], Bst + p * 2048 + kB[blk]);
            #pragma unroll
            for (int ma = 0; ma < 4; ma++)
                #pragma unroll
                for (int p = 0; p < 2; p++) {
                    mma_f16(acc[ma][2 * p],     a[ma][0], a[ma][1], a[ma][2], a[ma][3],
                            b[p][0], b[p][1]);
                    mma_f16(acc[ma][2 * p + 1], a[ma][0], a[ma][1], a[ma][2], a[ma][3],
                            b[p][2], b[p][3]);
                }
        }
    }

    // ---- epilogue: d^2 + dual-direction hardest pos/neg ----
    float apd2[8], and2[8];                 // row-side (rows of I)
    float colap[8], colan[8];               // col-side (rows of J), off-diag
    #pragma unroll
    for (int i = 0; i < 8; i++) {
        apd2[i] = 0.f; and2[i] = CUDART_INF_F;
        colap[i] = 0.f; colan[i] = CUDART_INF_F;
    }

    #pragma unroll
    for (int ma = 0; ma < 4; ma++) {
        #pragma unroll
        for (int h = 0; h < 2; h++) {
            const int rloc = wm * 64 + ma * 16 + gID + 8 * h;
            const int rT   = tRs[rloc];
            const float rS = sRs[rloc];
            const int ridx = ma * 2 + h;
            #pragma unroll
            for (int na = 0; na < 4; na++) {
                #pragma unroll
                for (int j = 0; j < 2; j++) {
                    const int col = wn * 32 + na * 8 + tig * 2 + j;
                    float d2 = rS + sCs[col] - 2.f * acc[ma][na][2 * h + j];
                    if (diag && rloc == col) d2 = EPS;
                    d2 = fmaxf(d2, EPS);
                    const bool same = (rT == tCs[col]);
                    const int cidx = na * 2 + j;
                    if (same) {
                        apd2[ridx]  = fmaxf(apd2[ridx],  d2);
                        colap[cidx] = fmaxf(colap[cidx], d2);
                    } else {
                        and2[ridx]  = fminf(and2[ridx],  d2);
                        colan[cidx] = fminf(colan[cidx], d2);
                    }
                }
            }
        }
    }

    // row-side: reduce across quad (tig), then atomics
    #pragma unroll
    for (int off = 1; off <= 2; off <<= 1)
        #pragma unroll
        for (int i = 0; i < 8; i++) {
            apd2[i] = fmaxf(apd2[i], __shfl_xor_sync(0xffffffffu, apd2[i], off));
            and2[i] = fminf(and2[i], __shfl_xor_sync(0xffffffffu, and2[i], off));
        }
    if (tig == 0) {
        #pragma unroll
        for (int ma = 0; ma < 4; ma++)
            #pragma unroll
            for (int h = 0; h < 2; h++) {
                int rg = rowBase + wm * 64 + ma * 16 + gID + 8 * h;
                atomicMax(&g_ap_bits[rg], __float_as_int(apd2[ma * 2 + h]));
                atomicMin(&g_an_bits[rg], __float_as_int(and2[ma * 2 + h]));
            }
    }

    // col-side (off-diagonal only): reduce across gID (lanes 4,8,16), atomics
    if (!diag) {
        #pragma unroll
        for (int off = 4; off <= 16; off <<= 1)
            #pragma unroll
            for (int i = 0; i < 8; i++) {
                colap[i] = fmaxf(colap[i], __shfl_xor_sync(0xffffffffu, colap[i], off));
                colan[i] = fminf(colan[i], __shfl_xor_sync(0xffffffffu, colan[i], off));
            }
        if (gID == 0) {
            #pragma unroll
            for (int na = 0; na < 4; na++)
                #pragma unroll
                for (int j = 0; j < 2; j++) {
                    int cg = colBase + wn * 32 + na * 8 + tig * 2 + j;
                    atomicMax(&g_ap_bits[cg], __float_as_int(colap[na * 2 + j]));
                    atomicMin(&g_an_bits[cg], __float_as_int(colan[na * 2 + j]));
                }
        }
    }
}

// ---------------- final mean(relu(sqrt(ap2) - sqrt(an2) + margin)) --------
__global__ void loss_kernel(int n, float* __restrict__ out) {
    __shared__ float red[8];
    int tid = threadIdx.x;
    float s = 0.f;
    for (int i = tid; i < n; i += 256) {
        float ap = sqrtf(fmaxf(__int_as_float(g_ap_bits[i]), EPS));
        float an = sqrtf(fmaxf(__int_as_float(g_an_bits[i]), EPS));
        s += fmaxf(ap - an + MARGIN, 0.f);
    }
    #pragma unroll
    for (int off = 16; off; off >>= 1)
        s += __shfl_xor_sync(0xffffffffu, s, off);
    if ((tid & 31) == 0) red[tid >> 5] = s;
    __syncthreads();
    if (tid < 32) {
        s = (tid < 8) ? red[tid] : 0.f;
        #pragma unroll
        for (int off = 4; off; off >>= 1)
            s += __shfl_xor_sync(0xffffffffu, s, off);
        if (tid == 0) out[0] = s / (float)n;
    }
}

extern "C" void kernel_launch(void* const* d_in, const int* in_sizes, int n_in,
                              void* d_out, int out_size) {
    const float* X    = (const float*)d_in[0];
    const int*   traw = (const int*)d_in[1];
    float* out = (float*)d_out;
    int n = in_sizes[1];
    int d = in_sizes[0] / n;

    int dynBytes = 3 * 32768;              // 3-stage pipeline (A+B per stage)
    cudaFuncSetAttribute(dist_mma_kernel,
                         cudaFuncAttributeMaxDynamicSharedMemorySize, dynBytes);

    label_kernel<<<1, 256>>>(traw, n);

    int warpsPerBlock = 8;
    int nb = (n + warpsPerBlock - 1) / warpsPerBlock;
    prep_kernel<<<nb, warpsPerBlock * 32>>>(X, n, d);

    int nB = n >> 7;
    int nPairs = nB * (nB + 1) / 2;
    dist_mma_kernel<<<nPairs, 256, dynBytes>>>(n, d);

    loss_kernel<<<1, 256>>>(n, out);
}

// round 15
// speedup vs baseline: 2.2491x; 1.1244x over previous
#include <cuda_runtime.h>
#include <cuda_fp16.h>
#include <math_constants.h>
#include <cstdint>

#define NMAX 16384
#define DMAX 512
#define MARGIN 0.3f
#define EPS 1e-12f

#define RED_BLOCKS 64

__device__ float  g_sq[NMAX];
__device__ int    g_lab[NMAX];
__device__ int    g_ap_bits[NMAX];
__device__ int    g_an_bits[NMAX];
__device__ float  g_part[RED_BLOCKS];
__device__ __half g_xh[(size_t)NMAX * DMAX];

// ---------------- PTX helpers ----------------
__device__ __forceinline__ uint32_t smem_u32(const void* p) {
    uint32_t a;
    asm("{ .reg .u64 t; cvta.to.shared.u64 t, %1; cvt.u32.u64 %0, t; }"
        : "=r"(a) : "l"(p));
    return a;
}
#define CP_ASYNC16(dst, src) \
    asm volatile("cp.async.cg.shared.global [%0], [%1], 16;" \
                 :: "r"(dst), "l"(src) : "memory")
#define CP_COMMIT() asm volatile("cp.async.commit_group;" ::: "memory")
#define CP_WAIT1()  asm volatile("cp.async.wait_group 1;" ::: "memory")

__device__ __forceinline__ void ldsm_x4(uint32_t* r, uint32_t addr) {
    asm volatile("ldmatrix.sync.aligned.m8n8.x4.shared.b16 {%0,%1,%2,%3}, [%4];"
                 : "=r"(r[0]), "=r"(r[1]), "=r"(r[2]), "=r"(r[3]) : "r"(addr));
}
__device__ __forceinline__ void mma_f16(float* c, uint32_t a0, uint32_t a1,
                                        uint32_t a2, uint32_t a3,
                                        uint32_t b0, uint32_t b1) {
    asm volatile(
        "mma.sync.aligned.m16n8k16.row.col.f32.f16.f16.f32 "
        "{%0,%1,%2,%3}, {%4,%5,%6,%7}, {%8,%9}, {%0,%1,%2,%3};"
        : "+f"(c[0]), "+f"(c[1]), "+f"(c[2]), "+f"(c[3])
        : "r"(a0), "r"(a1), "r"(a2), "r"(a3), "r"(b0), "r"(b1));
}

// ---- labels (int32 or int64 on disk) -> g_lab int32; also init ap/an ----
__global__ void label_kernel(const int* __restrict__ traw, int n) {
    __shared__ int odd_nonzero;
    if (threadIdx.x == 0) odd_nonzero = 0;
    __syncthreads();
    int m = (n < 128) ? n : 128;
    for (int i = threadIdx.x; i < m; i += blockDim.x)
        if (traw[2 * i + 1] != 0) atomicOr(&odd_nonzero, 1);
    __syncthreads();
    bool is64 = (odd_nonzero == 0);
    for (int i = threadIdx.x; i < n; i += blockDim.x) {
        g_lab[i] = is64 ? traw[2 * i] : traw[i];
        g_ap_bits[i] = 0;
        g_an_bits[i] = 0x7f800000;
    }
}

// ---- fused fp32->fp16 convert + exact fp32 sq-norm: one warp per row ----
__global__ void prep_kernel(const float* __restrict__ X, int n, int d) {
    int warp = (blockIdx.x * blockDim.x + threadIdx.x) >> 5;
    int lane = threadIdx.x & 31;
    if (warp >= n) return;
    const float4* row = (const float4*)(X + (size_t)warp * d);
    __half2* orow = (__half2*)(g_xh + (size_t)warp * d);
    float s = 0.f;
    for (int k = lane; k < d / 4; k += 32) {
        float4 v = row[k];
        s = fmaf(v.x, v.x, s); s = fmaf(v.y, v.y, s);
        s = fmaf(v.z, v.z, s); s = fmaf(v.w, v.w, s);
        orow[2 * k]     = __floats2half2_rn(v.x, v.y);
        orow[2 * k + 1] = __floats2half2_rn(v.z, v.w);
    }
    #pragma unroll
    for (int off = 16; off; off >>= 1)
        s += __shfl_xor_sync(0xffffffffu, s, off);
    if (lane == 0) g_sq[warp] = s;
}

// --------- symmetric fp16 mma gram + d^2 + hardest pos/neg ----------
// One CTA per block-pair (I <= J) of 128x128. Off-diagonal CTAs update both
// row-side (rows of I) and col-side (rows of J) reductions from one GEMM.
// 8 warps (2 M x 4 N), warp tile 64x32, 3-stage cp.async pipeline.
__global__ __launch_bounds__(256, 2)
void dist_mma_kernel(int n, int d) {
    extern __shared__ char dyn[];
    __shared__ int   tRs[128];
    __shared__ float sRs[128];
    __shared__ int   tCs[128];
    __shared__ float sCs[128];

    const int tid  = threadIdx.x;          // 256 threads = 8 warps
    const int wid  = tid >> 5;
    const int lane = tid & 31;
    const int wm   = wid & 1;              // 2 warps along M (64 rows each)
    const int wn   = wid >> 1;             // 4 warps along N (32 cols each)
    const int gID  = lane >> 2;
    const int tig  = lane & 3;

    // ---- triangle mapping: blockIdx.x -> (I, J), I <= J ----
    const int nB = n >> 7;
    const int idx = blockIdx.x;
    // f(i) = pairs before row i = i*nB - i*(i-1)/2
    int I = (int)((2.f * nB + 1.f -
                   sqrtf((2.f * nB + 1.f) * (2.f * nB + 1.f) - 8.f * (float)idx)) * 0.5f);
    if (I < 0) I = 0;
    if (I > nB - 1) I = nB - 1;
    while (I > 0 && (I * nB - (I * (I - 1)) / 2) > idx) I--;
    while (((I + 1) * nB - ((I + 1) * I) / 2) <= idx) I++;
    const int J = I + (idx - (I * nB - (I * (I - 1)) / 2));
    const bool diag = (I == J);

    const int rowBase = I << 7;
    const int colBase = J << 7;
    const int nSt = d >> 6;                // 64-half K stages (8 for d=512)

    const uint32_t dynbase = smem_u32(dyn);
    const __half* Xh = g_xh;

    // metadata
    if (tid < 128)       { tRs[tid] = g_lab[rowBase + tid];
                           sRs[tid] = g_sq[rowBase + tid]; }
    else                 { tCs[tid - 128] = g_lab[colBase + tid - 128];
                           sCs[tid - 128] = g_sq[colBase + tid - 128]; }

    // ---- pipeline prologue: stages 0, 1 ----
    #pragma unroll
    for (int st = 0; st < 2; st++) {
        uint32_t bufA = dynbase + st * 32768;
        uint32_t bufB = bufA + 16384;
        #pragma unroll
        for (int u = 0; u < 4; u++) {
            int t2 = u * 256 + tid;
            int r = t2 >> 3, q = t2 & 7;
            uint32_t off = r * 128 + ((q * 16) ^ ((r & 7) << 4));
            CP_ASYNC16(bufA + off, Xh + (size_t)(rowBase + r) * d + st * 64 + q * 8);
            CP_ASYNC16(bufB + off, Xh + (size_t)(colBase + r) * d + st * 64 + q * 8);
        }
        CP_COMMIT();
    }

    // frag address precompute (verified mapping from R11)
    const int xorv = (lane & 7) << 4;
    const uint32_t aRowOff = (uint32_t)(wm * 64 + (lane & 15)) * 128;
    const uint32_t bRowOff = (uint32_t)(wn * 32 + ((lane >> 4) & 1) * 8 + (lane & 7)) * 128;
    int kA[4], kB[4];
    #pragma unroll
    for (int blk = 0; blk < 4; blk++) {
        kA[blk] = (blk * 32 + (lane >> 4) * 16) ^ xorv;
        kB[blk] = (blk * 32 + ((lane >> 3) & 1) * 16) ^ xorv;
    }

    float acc[4][4][4];
    #pragma unroll
    for (int ma = 0; ma < 4; ma++)
        #pragma unroll
        for (int na = 0; na < 4; na++)
            #pragma unroll
            for (int f = 0; f < 4; f++) acc[ma][na][f] = 0.f;

    // ---- main K loop (pure GEMM) ----
    for (int k = 0; k < nSt; k++) {
        CP_WAIT1();
        __syncthreads();                   // stage k visible to all warps

        // prefetch stage k+2 into buffer (k+2)%3 (free: consumed at k-1)
        int k2 = k + 2;
        if (k2 < nSt) {
            uint32_t bufA = dynbase + (k2 % 3) * 32768;
            uint32_t bufB = bufA + 16384;
            #pragma unroll
            for (int u = 0; u < 4; u++) {
                int t2 = u * 256 + tid;
                int r = t2 >> 3, q = t2 & 7;
                uint32_t off = r * 128 + ((q * 16) ^ ((r & 7) << 4));
                CP_ASYNC16(bufA + off, Xh + (size_t)(rowBase + r) * d + k2 * 64 + q * 8);
                CP_ASYNC16(bufB + off, Xh + (size_t)(colBase + r) * d + k2 * 64 + q * 8);
            }
        }
        CP_COMMIT();

        const uint32_t Ast = dynbase + (k % 3) * 32768 + aRowOff;
        const uint32_t Bst = dynbase + (k % 3) * 32768 + 16384 + bRowOff;
        #pragma unroll
        for (int blk = 0; blk < 4; blk++) {
            uint32_t a[4][4], b[2][4];
            #pragma unroll
            for (int ma = 0; ma < 4; ma++)
                ldsm_x4(a[ma], Ast + ma * 2048 + kA[blk]);
            #pragma unroll
            for (int p = 0; p < 2; p++)
                ldsm_x4(b[p], Bst + p * 2048 + kB[blk]);
            #pragma unroll
            for (int ma = 0; ma < 4; ma++)
                #pragma unroll
                for (int p = 0; p < 2; p++) {
                    mma_f16(acc[ma][2 * p],     a[ma][0], a[ma][1], a[ma][2], a[ma][3],
                            b[p][0], b[p][1]);
                    mma_f16(acc[ma][2 * p + 1], a[ma][0], a[ma][1], a[ma][2], a[ma][3],
                            b[p][2], b[p][3]);
                }
        }
    }

    // ---- epilogue: d^2 + dual-direction hardest pos/neg ----
    float apd2[8], and2[8];                 // row-side (rows of I)
    float colap[8], colan[8];               // col-side (rows of J), off-diag
    #pragma unroll
    for (int i = 0; i < 8; i++) {
        apd2[i] = 0.f; and2[i] = CUDART_INF_F;
        colap[i] = 0.f; colan[i] = CUDART_INF_F;
    }

    #pragma unroll
    for (int ma = 0; ma < 4; ma++) {
        #pragma unroll
        for (int h = 0; h < 2; h++) {
            const int rloc = wm * 64 + ma * 16 + gID + 8 * h;
            const int rT   = tRs[rloc];
            const float rS = sRs[rloc];
            const int ridx = ma * 2 + h;
            #pragma unroll
            for (int na = 0; na < 4; na++) {
                #pragma unroll
                for (int j = 0; j < 2; j++) {
                    const int col = wn * 32 + na * 8 + tig * 2 + j;
                    float d2 = rS + sCs[col] - 2.f * acc[ma][na][2 * h + j];
                    if (diag && rloc == col) d2 = EPS;
                    d2 = fmaxf(d2, EPS);
                    const bool same = (rT == tCs[col]);
                    const int cidx = na * 2 + j;
                    if (same) {
                        apd2[ridx]  = fmaxf(apd2[ridx],  d2);
                        colap[cidx] = fmaxf(colap[cidx], d2);
                    } else {
                        and2[ridx]  = fminf(and2[ridx],  d2);
                        colan[cidx] = fminf(colan[cidx], d2);
                    }
                }
            }
        }
    }

    // row-side: reduce across quad (tig), then atomics
    #pragma unroll
    for (int off = 1; off <= 2; off <<= 1)
        #pragma unroll
        for (int i = 0; i < 8; i++) {
            apd2[i] = fmaxf(apd2[i], __shfl_xor_sync(0xffffffffu, apd2[i], off));
            and2[i] = fminf(and2[i], __shfl_xor_sync(0xffffffffu, and2[i], off));
        }
    if (tig == 0) {
        #pragma unroll
        for (int ma = 0; ma < 4; ma++)
            #pragma unroll
            for (int h = 0; h < 2; h++) {
                int rg = rowBase + wm * 64 + ma * 16 + gID + 8 * h;
                atomicMax(&g_ap_bits[rg], __float_as_int(apd2[ma * 2 + h]));
                atomicMin(&g_an_bits[rg], __float_as_int(and2[ma * 2 + h]));
            }
    }

    // col-side (off-diagonal only): reduce across gID (lanes 4,8,16), atomics
    if (!diag) {
        #pragma unroll
        for (int off = 4; off <= 16; off <<= 1)
            #pragma unroll
            for (int i = 0; i < 8; i++) {
                colap[i] = fmaxf(colap[i], __shfl_xor_sync(0xffffffffu, colap[i], off));
                colan[i] = fminf(colan[i], __shfl_xor_sync(0xffffffffu, colan[i], off));
            }
        if (gID == 0) {
            #pragma unroll
            for (int na = 0; na < 4; na++)
                #pragma unroll
                for (int j = 0; j < 2; j++) {
                    int cg = colBase + wn * 32 + na * 8 + tig * 2 + j;
                    atomicMax(&g_ap_bits[cg], __float_as_int(colap[na * 2 + j]));
                    atomicMin(&g_an_bits[cg], __float_as_int(colan[na * 2 + j]));
                }
        }
    }
}

// ---------------- loss phase 1: per-block partial sums (deterministic) -----
__global__ void loss1_kernel(int n, int per_block) {
    __shared__ float red[8];
    const int tid = threadIdx.x;
    const int base = blockIdx.x * per_block;
    const int end  = min(base + per_block, n);
    float s = 0.f;
    for (int i = base + tid; i < end; i += 256) {
        float ap = sqrtf(fmaxf(__int_as_float(g_ap_bits[i]), EPS));
        float an = sqrtf(fmaxf(__int_as_float(g_an_bits[i]), EPS));
        s += fmaxf(ap - an + MARGIN, 0.f);
    }
    #pragma unroll
    for (int off = 16; off; off >>= 1)
        s += __shfl_xor_sync(0xffffffffu, s, off);
    if ((tid & 31) == 0) red[tid >> 5] = s;
    __syncthreads();
    if (tid < 32) {
        s = (tid < 8) ? red[tid] : 0.f;
        #pragma unroll
        for (int off = 4; off; off >>= 1)
            s += __shfl_xor_sync(0xffffffffu, s, off);
        if (tid == 0) g_part[blockIdx.x] = s;
    }
}

// ---------------- loss phase 2: finalize ----------------
__global__ void loss2_kernel(int n, float* __restrict__ out) {
    int tid = threadIdx.x;                 // 64 threads
    float s = g_part[tid];
    #pragma unroll
    for (int off = 16; off; off >>= 1)
        s += __shfl_xor_sync(0xffffffffu, s, off);
    __shared__ float w0, w1;
    if (tid == 0)  w0 = s;
    if (tid == 32) w1 = s;
    __syncthreads();
    if (tid == 0) out[0] = (w0 + w1) / (float)n;
}

extern "C" void kernel_launch(void* const* d_in, const int* in_sizes, int n_in,
                              void* d_out, int out_size) {
    const float* X    = (const float*)d_in[0];
    const int*   traw = (const int*)d_in[1];
    float* out = (float*)d_out;
    int n = in_sizes[1];
    int d = in_sizes[0] / n;

    int dynBytes = 3 * 32768;              // 3-stage pipeline (A+B per stage)
    cudaFuncSetAttribute(dist_mma_kernel,
                         cudaFuncAttributeMaxDynamicSharedMemorySize, dynBytes);

    label_kernel<<<1, 256>>>(traw, n);

    int warpsPerBlock = 8;
    int nb = (n + warpsPerBlock - 1) / warpsPerBlock;
    prep_kernel<<<nb, warpsPerBlock * 32>>>(X, n, d);

    int nB = n >> 7;
    int nPairs = nB * (nB + 1) / 2;
    dist_mma_kernel<<<nPairs, 256, dynBytes>>>(n, d);

    int per_block = (n + RED_BLOCKS - 1) / RED_BLOCKS;
    loss1_kernel<<<RED_BLOCKS, 256>>>(n, per_block);
    loss2_kernel<<<1, 64>>>(n, out);
}

// round 17
// speedup vs baseline: 2.3899x; 1.0626x over previous
#include <cuda_runtime.h>
#include <cuda_fp16.h>
#include <math_constants.h>
#include <cstdint>

#define NMAX 16384
#define DMAX 512
#define MARGIN 0.3f
#define EPS 1e-12f

#define RED_BLOCKS 64

__device__ float  g_sq[NMAX];
__device__ int    g_lab[NMAX];
__device__ int    g_ap_bits[NMAX];
__device__ int    g_an_bits[NMAX];
__device__ float  g_part[RED_BLOCKS];
__device__ __half g_xh[(size_t)NMAX * DMAX];

// ---------------- PTX helpers ----------------
__device__ __forceinline__ uint32_t smem_u32(const void* p) {
    uint32_t a;
    asm("{ .reg .u64 t; cvta.to.shared.u64 t, %1; cvt.u32.u64 %0, t; }"
        : "=r"(a) : "l"(p));
    return a;
}
#define CP_ASYNC16(dst, src) \
    asm volatile("cp.async.cg.shared.global [%0], [%1], 16;" \
                 :: "r"(dst), "l"(src) : "memory")
#define CP_COMMIT() asm volatile("cp.async.commit_group;" ::: "memory")
#define CP_WAIT1()  asm volatile("cp.async.wait_group 1;" ::: "memory")

__device__ __forceinline__ void ldsm_x4(uint32_t* r, uint32_t addr) {
    asm volatile("ldmatrix.sync.aligned.m8n8.x4.shared.b16 {%0,%1,%2,%3}, [%4];"
                 : "=r"(r[0]), "=r"(r[1]), "=r"(r[2]), "=r"(r[3]) : "r"(addr));
}
__device__ __forceinline__ void mma_f16(float* c, uint32_t a0, uint32_t a1,
                                        uint32_t a2, uint32_t a3,
                                        uint32_t b0, uint32_t b1) {
    asm volatile(
        "mma.sync.aligned.m16n8k16.row.col.f32.f16.f16.f32 "
        "{%0,%1,%2,%3}, {%4,%5,%6,%7}, {%8,%9}, {%0,%1,%2,%3};"
        : "+f"(c[0]), "+f"(c[1]), "+f"(c[2]), "+f"(c[3])
        : "r"(a0), "r"(a1), "r"(a2), "r"(a3), "r"(b0), "r"(b1));
}

// ---- labels (int32 or int64 on disk) -> g_lab int32; also init ap/an ----
// Multi-block: each block redundantly detects dtype (cheap: 128 loads),
// then grid-strides its slice of canonicalize + init.
__global__ void label_kernel(const int* __restrict__ traw, int n) {
    __shared__ int odd_nonzero;
    if (threadIdx.x == 0) odd_nonzero = 0;
    __syncthreads();
    int m = (n < 128) ? n : 128;
    for (int i = threadIdx.x; i < m; i += blockDim.x)
        if (traw[2 * i + 1] != 0) atomicOr(&odd_nonzero, 1);
    __syncthreads();
    bool is64 = (odd_nonzero == 0);
    const int stride = gridDim.x * blockDim.x;
    for (int i = blockIdx.x * blockDim.x + threadIdx.x; i < n; i += stride) {
        g_lab[i] = is64 ? traw[2 * i] : traw[i];
        g_ap_bits[i] = 0;
        g_an_bits[i] = 0x7f800000;
    }
}

// ---- fused fp32->fp16 convert + exact fp32 sq-norm: one warp per row ----
__global__ void prep_kernel(const float* __restrict__ X, int n, int d) {
    int warp = (blockIdx.x * blockDim.x + threadIdx.x) >> 5;
    int lane = threadIdx.x & 31;
    if (warp >= n) return;
    const float4* row = (const float4*)(X + (size_t)warp * d);
    __half2* orow = (__half2*)(g_xh + (size_t)warp * d);
    float s = 0.f;
    for (int k = lane; k < d / 4; k += 32) {
        float4 v = row[k];
        s = fmaf(v.x, v.x, s); s = fmaf(v.y, v.y, s);
        s = fmaf(v.z, v.z, s); s = fmaf(v.w, v.w, s);
        orow[2 * k]     = __floats2half2_rn(v.x, v.y);
        orow[2 * k + 1] = __floats2half2_rn(v.z, v.w);
    }
    #pragma unroll
    for (int off = 16; off; off >>= 1)
        s += __shfl_xor_sync(0xffffffffu, s, off);
    if (lane == 0) g_sq[warp] = s;
}

// --------- symmetric fp16 mma gram + d^2 + hardest pos/neg ----------
// One CTA per block-pair (I <= J) of 128x128. Off-diagonal CTAs update both
// row-side (rows of I) and col-side (rows of J) reductions from one GEMM.
// 8 warps (2 M x 4 N), warp tile 64x32, 3-stage cp.async pipeline.
__global__ __launch_bounds__(256, 2)
void dist_mma_kernel(int n, int d) {
    extern __shared__ char dyn[];
    __shared__ int   tRs[128];
    __shared__ float sRs[128];
    __shared__ int   tCs[128];
    __shared__ float sCs[128];

    const int tid  = threadIdx.x;          // 256 threads = 8 warps
    const int wid  = tid >> 5;
    const int lane = tid & 31;
    const int wm   = wid & 1;              // 2 warps along M (64 rows each)
    const int wn   = wid >> 1;             // 4 warps along N (32 cols each)
    const int gID  = lane >> 2;
    const int tig  = lane & 3;

    // ---- triangle mapping: blockIdx.x -> (I, J), I <= J ----
    const int nB = n >> 7;
    const int idx = blockIdx.x;
    // f(i) = pairs before row i = i*nB - i*(i-1)/2
    int I = (int)((2.f * nB + 1.f -
                   sqrtf((2.f * nB + 1.f) * (2.f * nB + 1.f) - 8.f * (float)idx)) * 0.5f);
    if (I < 0) I = 0;
    if (I > nB - 1) I = nB - 1;
    while (I > 0 && (I * nB - (I * (I - 1)) / 2) > idx) I--;
    while (((I + 1) * nB - ((I + 1) * I) / 2) <= idx) I++;
    const int J = I + (idx - (I * nB - (I * (I - 1)) / 2));
    const bool diag = (I == J);

    const int rowBase = I << 7;
    const int colBase = J << 7;
    const int nSt = d >> 6;                // 64-half K stages (8 for d=512)

    const uint32_t dynbase = smem_u32(dyn);
    const __half* Xh = g_xh;

    // metadata
    if (tid < 128)       { tRs[tid] = g_lab[rowBase + tid];
                           sRs[tid] = g_sq[rowBase + tid]; }
    else                 { tCs[tid - 128] = g_lab[colBase + tid - 128];
                           sCs[tid - 128] = g_sq[colBase + tid - 128]; }

    // ---- pipeline prologue: stages 0, 1 ----
    #pragma unroll
    for (int st = 0; st < 2; st++) {
        uint32_t bufA = dynbase + st * 32768;
        uint32_t bufB = bufA + 16384;
        #pragma unroll
        for (int u = 0; u < 4; u++) {
            int t2 = u * 256 + tid;
            int r = t2 >> 3, q = t2 & 7;
            uint32_t off = r * 128 + ((q * 16) ^ ((r & 7) << 4));
            CP_ASYNC16(bufA + off, Xh + (size_t)(rowBase + r) * d + st * 64 + q * 8);
            CP_ASYNC16(bufB + off, Xh + (size_t)(colBase + r) * d + st * 64 + q * 8);
        }
        CP_COMMIT();
    }

    // frag address precompute (verified mapping from R11)
    const int xorv = (lane & 7) << 4;
    const uint32_t aRowOff = (uint32_t)(wm * 64 + (lane & 15)) * 128;
    const uint32_t bRowOff = (uint32_t)(wn * 32 + ((lane >> 4) & 1) * 8 + (lane & 7)) * 128;
    int kA[4], kB[4];
    #pragma unroll
    for (int blk = 0; blk < 4; blk++) {
        kA[blk] = (blk * 32 + (lane >> 4) * 16) ^ xorv;
        kB[blk] = (blk * 32 + ((lane >> 3) & 1) * 16) ^ xorv;
    }

    float acc[4][4][4];
    #pragma unroll
    for (int ma = 0; ma < 4; ma++)
        #pragma unroll
        for (int na = 0; na < 4; na++)
            #pragma unroll
            for (int f = 0; f < 4; f++) acc[ma][na][f] = 0.f;

    // ---- main K loop (pure GEMM) ----
    for (int k = 0; k < nSt; k++) {
        CP_WAIT1();
        __syncthreads();                   // stage k visible to all warps

        // prefetch stage k+2 into buffer (k+2)%3 (free: consumed at k-1)
        int k2 = k + 2;
        if (k2 < nSt) {
            uint32_t bufA = dynbase + (k2 % 3) * 32768;
            uint32_t bufB = bufA + 16384;
            #pragma unroll
            for (int u = 0; u < 4; u++) {
                int t2 = u * 256 + tid;
                int r = t2 >> 3, q = t2 & 7;
                uint32_t off = r * 128 + ((q * 16) ^ ((r & 7) << 4));
                CP_ASYNC16(bufA + off, Xh + (size_t)(rowBase + r) * d + k2 * 64 + q * 8);
                CP_ASYNC16(bufB + off, Xh + (size_t)(colBase + r) * d + k2 * 64 + q * 8);
            }
        }
        CP_COMMIT();

        const uint32_t Ast = dynbase + (k % 3) * 32768 + aRowOff;
        const uint32_t Bst = dynbase + (k % 3) * 32768 + 16384 + bRowOff;
        #pragma unroll
        for (int blk = 0; blk < 4; blk++) {
            uint32_t a[4][4], b[2][4];
            #pragma unroll
            for (int ma = 0; ma < 4; ma++)
                ldsm_x4(a[ma], Ast + ma * 2048 + kA[blk]);
            #pragma unroll
            for (int p = 0; p < 2; p++)
                ldsm_x4(b[p], Bst + p * 2048 + kB[blk]);
            #pragma unroll
            for (int ma = 0; ma < 4; ma++)
                #pragma unroll
                for (int p = 0; p < 2; p++) {
                    mma_f16(acc[ma][2 * p],     a[ma][0], a[ma][1], a[ma][2], a[ma][3],
                            b[p][0], b[p][1]);
                    mma_f16(acc[ma][2 * p + 1], a[ma][0], a[ma][1], a[ma][2], a[ma][3],
                            b[p][2], b[p][3]);
                }
        }
    }

    // ---- epilogue: d^2 + dual-direction hardest pos/neg ----
    float apd2[8], and2[8];                 // row-side (rows of I)
    float colap[8], colan[8];               // col-side (rows of J), off-diag
    #pragma unroll
    for (int i = 0; i < 8; i++) {
        apd2[i] = 0.f; and2[i] = CUDART_INF_F;
        colap[i] = 0.f; colan[i] = CUDART_INF_F;
    }

    #pragma unroll
    for (int ma = 0; ma < 4; ma++) {
        #pragma unroll
        for (int h = 0; h < 2; h++) {
            const int rloc = wm * 64 + ma * 16 + gID + 8 * h;
            const int rT   = tRs[rloc];
            const float rS = sRs[rloc];
            const int ridx = ma * 2 + h;
            #pragma unroll
            for (int na = 0; na < 4; na++) {
                #pragma unroll
                for (int j = 0; j < 2; j++) {
                    const int col = wn * 32 + na * 8 + tig * 2 + j;
                    float d2 = rS + sCs[col] - 2.f * acc[ma][na][2 * h + j];
                    if (diag && rloc == col) d2 = EPS;
                    d2 = fmaxf(d2, EPS);
                    const bool same = (rT == tCs[col]);
                    const int cidx = na * 2 + j;
                    if (same) {
                        apd2[ridx]  = fmaxf(apd2[ridx],  d2);
                        colap[cidx] = fmaxf(colap[cidx], d2);
                    } else {
                        and2[ridx]  = fminf(and2[ridx],  d2);
                        colan[cidx] = fminf(colan[cidx], d2);
                    }
                }
            }
        }
    }

    // row-side: reduce across quad (tig), then atomics
    #pragma unroll
    for (int off = 1; off <= 2; off <<= 1)
        #pragma unroll
        for (int i = 0; i < 8; i++) {
            apd2[i] = fmaxf(apd2[i], __shfl_xor_sync(0xffffffffu, apd2[i], off));
            and2[i] = fminf(and2[i], __shfl_xor_sync(0xffffffffu, and2[i], off));
        }
    if (tig == 0) {
        #pragma unroll
        for (int ma = 0; ma < 4; ma++)
            #pragma unroll
            for (int h = 0; h < 2; h++) {
                int rg = rowBase + wm * 64 + ma * 16 + gID + 8 * h;
                atomicMax(&g_ap_bits[rg], __float_as_int(apd2[ma * 2 + h]));
                atomicMin(&g_an_bits[rg], __float_as_int(and2[ma * 2 + h]));
            }
    }

    // col-side (off-diagonal only): reduce across gID (lanes 4,8,16), atomics
    if (!diag) {
        #pragma unroll
        for (int off = 4; off <= 16; off <<= 1)
            #pragma unroll
            for (int i = 0; i < 8; i++) {
                colap[i] = fmaxf(colap[i], __shfl_xor_sync(0xffffffffu, colap[i], off));
                colan[i] = fminf(colan[i], __shfl_xor_sync(0xffffffffu, colan[i], off));
            }
        if (gID == 0) {
            #pragma unroll
            for (int na = 0; na < 4; na++)
                #pragma unroll
                for (int j = 0; j < 2; j++) {
                    int cg = colBase + wn * 32 + na * 8 + tig * 2 + j;
                    atomicMax(&g_ap_bits[cg], __float_as_int(colap[na * 2 + j]));
                    atomicMin(&g_an_bits[cg], __float_as_int(colan[na * 2 + j]));
                }
        }
    }
}

// ---------------- loss phase 1: per-block partial sums (deterministic) -----
__global__ void loss1_kernel(int n, int per_block) {
    __shared__ float red[8];
    const int tid = threadIdx.x;
    const int base = blockIdx.x * per_block;
    const int end  = min(base + per_block, n);
    float s = 0.f;
    for (int i = base + tid; i < end; i += 256) {
        float ap = sqrtf(fmaxf(__int_as_float(g_ap_bits[i]), EPS));
        float an = sqrtf(fmaxf(__int_as_float(g_an_bits[i]), EPS));
        s += fmaxf(ap - an + MARGIN, 0.f);
    }
    #pragma unroll
    for (int off = 16; off; off >>= 1)
        s += __shfl_xor_sync(0xffffffffu, s, off);
    if ((tid & 31) == 0) red[tid >> 5] = s;
    __syncthreads();
    if (tid < 32) {
        s = (tid < 8) ? red[tid] : 0.f;
        #pragma unroll
        for (int off = 4; off; off >>= 1)
            s += __shfl_xor_sync(0xffffffffu, s, off);
        if (tid == 0) g_part[blockIdx.x] = s;
    }
}

// ---------------- loss phase 2: finalize (single warp) ----------------
__global__ void loss2_kernel(int n, float* __restrict__ out) {
    int tid = threadIdx.x;                 // 32 threads
    float s = g_part[tid] + g_part[tid + 32];
    #pragma unroll
    for (int off = 16; off; off >>= 1)
        s += __shfl_xor_sync(0xffffffffu, s, off);
    if (tid == 0) out[0] = s / (float)n;
}

extern "C" void kernel_launch(void* const* d_in, const int* in_sizes, int n_in,
                              void* d_out, int out_size) {
    const float* X    = (const float*)d_in[0];
    const int*   traw = (const int*)d_in[1];
    float* out = (float*)d_out;
    int n = in_sizes[1];
    int d = in_sizes[0] / n;

    int dynBytes = 3 * 32768;              // 3-stage pipeline (A+B per stage)
    cudaFuncSetAttribute(dist_mma_kernel,
                         cudaFuncAttributeMaxDynamicSharedMemorySize, dynBytes);

    label_kernel<<<32, 256>>>(traw, n);

    int warpsPerBlock = 8;
    int nb = (n + warpsPerBlock - 1) / warpsPerBlock;
    prep_kernel<<<nb, warpsPerBlock * 32>>>(X, n, d);

    int nB = n >> 7;
    int nPairs = nB * (nB + 1) / 2;
    dist_mma_kernel<<<nPairs, 256, dynBytes>>>(n, d);

    int per_block = (n + RED_BLOCKS - 1) / RED_BLOCKS;
    loss1_kernel<<<RED_BLOCKS, 256>>>(n, per_block);
    loss2_kernel<<<1, 32>>>(n, out);
}